// round 6
// baseline (speedup 1.0000x reference)
#include <cuda_runtime.h>

// Sliding-window (no-overlap chunk) attention, fp32 with packed f32x2 FMA.
// B=4, S=8192, H=16, D=64, window w=128, C=64 chunks.
// Outputs: out [B,S,H,64] then attn [B,S,H,384] concatenated in d_out.

constexpr int Bc = 4;
constexpr int Sc = 8192;
constexpr int Hc = 16;
constexpr int Dc = 64;
constexpr int Wn = 128;          // window / chunk size
constexpr int Cc = Sc / Wn;      // 64 chunks
constexpr int QT = 32;           // queries per block
constexpr int NT = 256;          // threads per block
constexpr int PRS = 384;         // score row stride (floats)

// smem layout (floats)
constexpr int OFF_Q  = 0;                  // Qs2[64][32] duplicated pairs (d-major) = 4096 floats
constexpr int OFF_KV = 4096;               // Ks[64][128] transposed OR Vs[128][64] = 8192 floats
constexpr int OFF_P  = 4096 + 8192;        // Ps[32][384]
constexpr int SMEM_FLOATS = OFF_P + QT * PRS;   // 24576 floats = 96 KB

using ull = unsigned long long;

__device__ __forceinline__ void ffma2(ull& d, ull a, ull b) {
    asm("fma.rn.f32x2 %0, %1, %2, %0;" : "+l"(d) : "l"(a), "l"(b));
}
__device__ __forceinline__ ull dup2(float v) {
    ull r; asm("mov.b64 %0, {%1, %1};" : "=l"(r) : "f"(v)); return r;
}
__device__ __forceinline__ float2 u2f(ull v) {
    float2 f; asm("mov.b64 {%0, %1}, %2;" : "=f"(f.x), "=f"(f.y) : "l"(v)); return f;
}

__global__ __launch_bounds__(NT, 2)
void swa_noovl_kernel(const float* __restrict__ q,
                      const float* __restrict__ k,
                      const float* __restrict__ v,
                      float* __restrict__ out,
                      float* __restrict__ attn)
{
    extern __shared__ float sm[];
    float* Qs = sm + OFF_Q;      // duplicated-pair layout: row d has 64 floats (32 pairs)
    float* KV = sm + OFF_KV;
    float* Ps = sm + OFF_P;

    const int tid = threadIdx.x;
    const int c   = blockIdx.x >> 2;        // chunk
    const int qt  = blockIdx.x & 3;         // query sub-tile within chunk
    const int h   = blockIdx.y;
    const int b   = blockIdx.z;
    const int s0  = c * Wn + qt * QT;

    const size_t rowstride = (size_t)Hc * Dc;   // 1024 floats between seq positions

    // ---- Load Q tile transposed+duplicated: Qs2[d][y] = {q, q} ----
    {
        const float* qbase = q + ((size_t)b * Sc + s0) * rowstride + (size_t)h * Dc;
        int f = tid;
        #pragma unroll
        for (int i = 0; i < 2; i++) {          // 512 float4 total
            const int y = f & 31;
            const int g = f >> 5;              // dgroup 0..15
            const float4 val = *(const float4*)(qbase + (size_t)y * rowstride + g * 4);
            *(float2*)(Qs + (4 * g + 0) * 64 + 2 * y) = make_float2(val.x, val.x);
            *(float2*)(Qs + (4 * g + 1) * 64 + 2 * y) = make_float2(val.y, val.y);
            *(float2*)(Qs + (4 * g + 2) * 64 + 2 * y) = make_float2(val.z, val.z);
            *(float2*)(Qs + (4 * g + 3) * 64 + 2 * y) = make_float2(val.w, val.w);
            f += NT;
        }
    }

    // ================= QK^T : scores into Ps (f32x2 packed) =================
    const int r0 = (tid >> 5) * 4;    // GEMM1: 8 row-groups of 4
    const int c0 = (tid & 31) * 4;    //        32 col-groups of 4

    for (int e = 0; e < 3; e++) {
        const int kc = c - 1 + e;
        const bool valid = (kc >= 0) && (kc < Cc);
        __syncthreads();   // previous GEMM done reading KV
        if (valid) {
            // load K chunk transposed: Ks[d][y]
            const float* kbase = k + ((size_t)b * Sc + (size_t)kc * Wn) * rowstride + (size_t)h * Dc;
            int f = tid;
            #pragma unroll
            for (int i = 0; i < 8; i++) {      // 2048 float4 total
                const int y = f & 127;
                const int g = f >> 7;          // dgroup 0..15
                const float4 val = *(const float4*)(kbase + (size_t)y * rowstride + g * 4);
                KV[(4 * g + 0) * Wn + y] = val.x;
                KV[(4 * g + 1) * Wn + y] = val.y;
                KV[(4 * g + 2) * Wn + y] = val.z;
                KV[(4 * g + 3) * Wn + y] = val.w;
                f += NT;
            }
        }
        __syncthreads();
        if (valid) {
            ull acc[4][2];
            #pragma unroll
            for (int i = 0; i < 4; i++) { acc[i][0] = 0ull; acc[i][1] = 0ull; }

            #pragma unroll 8
            for (int d = 0; d < Dc; d++) {
                const ull* Qp = (const ull*)(Qs + d * 64);    // 32 dup-pairs
                const ulonglong2 A01 = *(const ulonglong2*)(Qp + r0);      // rows r0, r0+1 (bcast)
                const ulonglong2 A23 = *(const ulonglong2*)(Qp + r0 + 2);  // rows r0+2, r0+3
                const ulonglong2 Bv  = *(const ulonglong2*)(KV + d * Wn + c0);
                ffma2(acc[0][0], A01.x, Bv.x); ffma2(acc[0][1], A01.x, Bv.y);
                ffma2(acc[1][0], A01.y, Bv.x); ffma2(acc[1][1], A01.y, Bv.y);
                ffma2(acc[2][0], A23.x, Bv.x); ffma2(acc[2][1], A23.x, Bv.y);
                ffma2(acc[3][0], A23.y, Bv.x); ffma2(acc[3][1], A23.y, Bv.y);
            }
            #pragma unroll
            for (int i = 0; i < 4; i++) {
                const float2 lo = u2f(acc[i][0]);
                const float2 hi = u2f(acc[i][1]);
                *(float4*)(Ps + (size_t)(r0 + i) * PRS + e * Wn + c0) =
                    make_float4(lo.x, lo.y, hi.x, hi.y);
            }
        } else {
            // padded neighbor: exact score 0 (matches reference zero-padding)
            const int r    = tid >> 3;
            const int col0 = (tid & 7) * 16;
            const float4 z = make_float4(0.f, 0.f, 0.f, 0.f);
            #pragma unroll
            for (int j = 0; j < 4; j++)
                *(float4*)(Ps + (size_t)r * PRS + e * Wn + col0 + 4 * j) = z;
        }
    }
    __syncthreads();

    // ================= softmax over 384 + write attn =================
    {
        const int lane = tid & 31;
        const int w    = tid >> 5;
        #pragma unroll
        for (int rr = 0; rr < 4; rr++) {
            const int r = w * 4 + rr;
            float* prow = Ps + (size_t)r * PRS;
            float4 vv[3];
            float m = -3.402823466e38f;
            #pragma unroll
            for (int kk = 0; kk < 3; kk++) {
                vv[kk] = *(const float4*)(prow + kk * Wn + lane * 4);
                m = fmaxf(m, fmaxf(fmaxf(vv[kk].x, vv[kk].y), fmaxf(vv[kk].z, vv[kk].w)));
            }
            #pragma unroll
            for (int o = 16; o; o >>= 1)
                m = fmaxf(m, __shfl_xor_sync(0xffffffffu, m, o));

            float ssum = 0.0f;
            #pragma unroll
            for (int kk = 0; kk < 3; kk++) {
                vv[kk].x = __expf(vv[kk].x - m);
                vv[kk].y = __expf(vv[kk].y - m);
                vv[kk].z = __expf(vv[kk].z - m);
                vv[kk].w = __expf(vv[kk].w - m);
                ssum += vv[kk].x + vv[kk].y + vv[kk].z + vv[kk].w;
            }
            #pragma unroll
            for (int o = 16; o; o >>= 1)
                ssum += __shfl_xor_sync(0xffffffffu, ssum, o);

            const float inv = 1.0f / ssum;
            float* arow = attn + (((size_t)b * Sc + (s0 + r)) * Hc + h) * (size_t)(3 * Wn);
            #pragma unroll
            for (int kk = 0; kk < 3; kk++) {
                vv[kk].x *= inv; vv[kk].y *= inv; vv[kk].z *= inv; vv[kk].w *= inv;
                *(float4*)(prow + kk * Wn + lane * 4) = vv[kk];       // keep normalized P
                *(float4*)(arow + kk * Wn + lane * 4) = vv[kk];       // coalesced output
            }
        }
    }

    // ================= P @ V_ext (f32x2 packed) =================
    ull acc2[2][2];
    acc2[0][0] = 0ull; acc2[0][1] = 0ull; acc2[1][0] = 0ull; acc2[1][1] = 0ull;

    const int r0b = (tid >> 4) * 2;   // 16 row-groups of 2
    const int c0b = (tid & 15) * 4;   // 16 col-groups of 4

    for (int e = 0; e < 3; e++) {
        const int kc = c - 1 + e;
        if (kc < 0 || kc >= Cc) continue;   // uniform across block
        __syncthreads();   // prior GEMM2 done reading KV; softmax writes to Ps visible
        // load V chunk natural: Vs[y][d]
        const float* vbase = v + ((size_t)b * Sc + (size_t)kc * Wn) * rowstride + (size_t)h * Dc;
        int f = tid;
        #pragma unroll
        for (int i = 0; i < 8; i++) {
            const int y = f >> 4;
            const int g = f & 15;
            *(float4*)(KV + (size_t)y * Dc + g * 4) =
                *(const float4*)(vbase + (size_t)y * rowstride + g * 4);
            f += NT;
        }
        __syncthreads();

        const float* p0 = Ps + (size_t)(r0b + 0) * PRS + e * Wn;
        const float* p1 = Ps + (size_t)(r0b + 1) * PRS + e * Wn;
        #pragma unroll 4
        for (int y = 0; y < Wn; y += 4) {
            const float4 p0v = *(const float4*)(p0 + y);
            const float4 p1v = *(const float4*)(p1 + y);
            {
                const ulonglong2 Bv = *(const ulonglong2*)(KV + (size_t)(y + 0) * Dc + c0b);
                const ull A0 = dup2(p0v.x), A1 = dup2(p1v.x);
                ffma2(acc2[0][0], A0, Bv.x); ffma2(acc2[0][1], A0, Bv.y);
                ffma2(acc2[1][0], A1, Bv.x); ffma2(acc2[1][1], A1, Bv.y);
            }
            {
                const ulonglong2 Bv = *(const ulonglong2*)(KV + (size_t)(y + 1) * Dc + c0b);
                const ull A0 = dup2(p0v.y), A1 = dup2(p1v.y);
                ffma2(acc2[0][0], A0, Bv.x); ffma2(acc2[0][1], A0, Bv.y);
                ffma2(acc2[1][0], A1, Bv.x); ffma2(acc2[1][1], A1, Bv.y);
            }
            {
                const ulonglong2 Bv = *(const ulonglong2*)(KV + (size_t)(y + 2) * Dc + c0b);
                const ull A0 = dup2(p0v.z), A1 = dup2(p1v.z);
                ffma2(acc2[0][0], A0, Bv.x); ffma2(acc2[0][1], A0, Bv.y);
                ffma2(acc2[1][0], A1, Bv.x); ffma2(acc2[1][1], A1, Bv.y);
            }
            {
                const ulonglong2 Bv = *(const ulonglong2*)(KV + (size_t)(y + 3) * Dc + c0b);
                const ull A0 = dup2(p0v.w), A1 = dup2(p1v.w);
                ffma2(acc2[0][0], A0, Bv.x); ffma2(acc2[0][1], A0, Bv.y);
                ffma2(acc2[1][0], A1, Bv.x); ffma2(acc2[1][1], A1, Bv.y);
            }
        }
    }

    // write out [B,S,H,64]
    {
        float* obase = out + ((size_t)b * Sc + s0) * rowstride + (size_t)h * Dc;
        #pragma unroll
        for (int i = 0; i < 2; i++) {
            const float2 lo = u2f(acc2[i][0]);
            const float2 hi = u2f(acc2[i][1]);
            *(float4*)(obase + (size_t)(r0b + i) * rowstride + c0b) =
                make_float4(lo.x, lo.y, hi.x, hi.y);
        }
    }
}

extern "C" void kernel_launch(void* const* d_in, const int* in_sizes, int n_in,
                              void* d_out, int out_size)
{
    const float* q = (const float*)d_in[0];
    const float* k = (const float*)d_in[1];
    const float* v = (const float*)d_in[2];
    float* out  = (float*)d_out;
    float* attn = out + (size_t)Bc * Sc * Hc * Dc;   // out first, then attn

    cudaFuncSetAttribute(swa_noovl_kernel,
                         cudaFuncAttributeMaxDynamicSharedMemorySize,
                         SMEM_FLOATS * (int)sizeof(float));

    dim3 grid(Cc * 4, Hc, Bc);   // (chunk*4 + qtile, head, batch)
    swa_noovl_kernel<<<grid, NT, SMEM_FLOATS * sizeof(float)>>>(q, k, v, out, attn);
}

// round 8
// speedup vs baseline: 2.2679x; 2.2679x over previous
#include <cuda_runtime.h>
#include <cstdint>

// Sliding-window (no-overlap) attention via mma.sync bf16-split (HMMA path).
// B=4,S=8192,H=16,D=64,w=128,C=64. Block=(b,h,chunk,half): 64 queries, 256 thr.
// d_out = out [B,S,H,64] then attn [B,S,H,384].

constexpr int Bc = 4, Sc = 8192, Hc = 16, Wn = 128, Cc = 64, NT = 256;

// smem byte offsets
constexpr uint32_t OFF_QH  = 0;        // Qh [64][72] bf16
constexpr uint32_t OFF_QL  = 9216;     // Ql
constexpr uint32_t OFF_KVH = 18432;    // K/V staging hi [128][72] bf16
constexpr uint32_t OFF_KVL = 36864;    // lo
constexpr uint32_t OFF_PH  = 55296;    // P hi [64][392] bf16
constexpr uint32_t OFF_PL  = 105472;   // P lo
constexpr uint32_t OFF_SSUM = 155648;  // 64 floats
constexpr uint32_t SMEM_BYTES = 155648 + 256;

__device__ __forceinline__ uint32_t su32(const void* p) {
    uint32_t a;
    asm("{ .reg .u64 t; cvta.to.shared.u64 t, %1; cvt.u32.u64 %0, t; }" : "=r"(a) : "l"(p));
    return a;
}
// split (v0,v1) -> bf16x2 hi word + bf16x2 residual word (lo half = v0)
__device__ __forceinline__ void pack_split(float v0, float v1, uint32_t& hw, uint32_t& lw) {
    asm("cvt.rn.bf16x2.f32 %0, %1, %2;" : "=r"(hw) : "f"(v1), "f"(v0));
    float r0 = v0 - __uint_as_float(hw << 16);
    float r1 = v1 - __uint_as_float(hw & 0xffff0000u);
    asm("cvt.rn.bf16x2.f32 %0, %1, %2;" : "=r"(lw) : "f"(r1), "f"(r0));
}
__device__ __forceinline__ float blo(uint32_t w) { return __uint_as_float(w << 16); }
__device__ __forceinline__ float bhi(uint32_t w) { return __uint_as_float(w & 0xffff0000u); }

__device__ __forceinline__ void ldsm4(uint32_t* r, uint32_t a) {
    asm volatile("ldmatrix.sync.aligned.m8n8.x4.shared.b16 {%0,%1,%2,%3}, [%4];"
        : "=r"(r[0]), "=r"(r[1]), "=r"(r[2]), "=r"(r[3]) : "r"(a));
}
__device__ __forceinline__ void ldsm2(uint32_t* r, uint32_t a) {
    asm volatile("ldmatrix.sync.aligned.m8n8.x2.shared.b16 {%0,%1}, [%2];"
        : "=r"(r[0]), "=r"(r[1]) : "r"(a));
}
__device__ __forceinline__ void ldsm2t(uint32_t* r, uint32_t a) {
    asm volatile("ldmatrix.sync.aligned.m8n8.x2.trans.shared.b16 {%0,%1}, [%2];"
        : "=r"(r[0]), "=r"(r[1]) : "r"(a));
}
__device__ __forceinline__ void mma_bf16(float* d, const uint32_t* a, const uint32_t* b) {
    asm volatile("mma.sync.aligned.m16n8k16.row.col.f32.bf16.bf16.f32 "
        "{%0,%1,%2,%3}, {%4,%5,%6,%7}, {%8,%9}, {%0,%1,%2,%3};"
        : "+f"(d[0]), "+f"(d[1]), "+f"(d[2]), "+f"(d[3])
        : "r"(a[0]), "r"(a[1]), "r"(a[2]), "r"(a[3]), "r"(b[0]), "r"(b[1]));
}

__global__ void __launch_bounds__(NT, 1)
swa_mma_kernel(const float* __restrict__ q, const float* __restrict__ k,
               const float* __restrict__ v, float* __restrict__ out,
               float* __restrict__ attn)
{
    extern __shared__ char smc[];
    const uint32_t sb = su32(smc);
    const int tid = threadIdx.x, wid = tid >> 5, lane = tid & 31;
    const int hf = blockIdx.x & 1, c = blockIdx.x >> 1;
    const int h = blockIdx.y, b = blockIdx.z;
    const int s0 = c * Wn + hf * 64;
    const int e0 = (c > 0) ? 0 : 1, e1 = (c < Cc - 1) ? 2 : 1;

    float* ssum = (float*)(smc + OFF_SSUM);
    if (tid < 64) ssum[tid] = 128.0f * (float)(e0 + 2 - e1);   // padded-e cols: exp(0)=1

    const size_t hb = (size_t)h * 64;

    // ---- Q load + split into Qh/Ql [64][72] ----
    {
        const float* qb = q + (size_t)(b * Sc + s0) * 1024 + hb;
        #pragma unroll
        for (int i = 0; i < 4; i++) {
            int f = tid + i * NT, row = f >> 4, g = f & 15;
            float4 val = *(const float4*)(qb + (size_t)row * 1024 + g * 4);
            uint32_t h0, l0, h1, l1;
            pack_split(val.x, val.y, h0, l0);
            pack_split(val.z, val.w, h1, l1);
            *(uint2*)(smc + OFF_QH + row * 144 + g * 8) = make_uint2(h0, h1);
            *(uint2*)(smc + OFF_QL + row * 144 + g * 8) = make_uint2(l0, l1);
        }
    }

    const int mrow = (wid >> 1) * 16;   // warp query-row tile
    const int nk0  = (wid & 1) * 64;    // QK: kpos half
    const int nv0  = (wid & 1) * 32;    // PV: dim half
    float o[4][4];
    #pragma unroll
    for (int i = 0; i < 4; i++) { o[i][0] = o[i][1] = o[i][2] = o[i][3] = 0.f; }

    float4 kvreg[8];
    {   // preload K_{e0}
        const float* kb = k + (size_t)(b * Sc + (c - 1 + e0) * Wn) * 1024 + hb;
        #pragma unroll
        for (int i = 0; i < 8; i++) {
            int f = tid + i * NT;
            kvreg[i] = *(const float4*)(kb + (size_t)(f >> 4) * 1024 + (f & 15) * 4);
        }
    }

    for (int e = e0; e <= e1; e++) {
        __syncthreads();   // prior PV reads of KV done; Q visible (first iter)
        #pragma unroll
        for (int i = 0; i < 8; i++) {          // STS K
            int f = tid + i * NT, row = f >> 4, g = f & 15;
            float4 val = kvreg[i];
            uint32_t h0, l0, h1, l1;
            pack_split(val.x, val.y, h0, l0);
            pack_split(val.z, val.w, h1, l1);
            *(uint2*)(smc + OFF_KVH + row * 144 + g * 8) = make_uint2(h0, h1);
            *(uint2*)(smc + OFF_KVL + row * 144 + g * 8) = make_uint2(l0, l1);
        }
        {   // prefetch V_e
            const float* vb = v + (size_t)(b * Sc + (c - 1 + e) * Wn) * 1024 + hb;
            #pragma unroll
            for (int i = 0; i < 8; i++) {
                int f = tid + i * NT;
                kvreg[i] = *(const float4*)(vb + (size_t)(f >> 4) * 1024 + (f & 15) * 4);
            }
        }
        __syncthreads();   // K visible

        // ---- QK: warp tile 16x64, split-bf16 3 passes ----
        float sc[8][4];
        #pragma unroll
        for (int nt = 0; nt < 8; nt++) { sc[nt][0] = sc[nt][1] = sc[nt][2] = sc[nt][3] = 0.f; }
        #pragma unroll
        for (int kt = 0; kt < 4; kt++) {
            uint32_t ah[4], al[4];
            uint32_t ab = (uint32_t)(mrow + (lane & 15)) * 144u +
                          (uint32_t)(kt * 16 + (lane >> 4) * 8) * 2u;
            ldsm4(ah, sb + OFF_QH + ab);
            ldsm4(al, sb + OFF_QL + ab);
            #pragma unroll
            for (int nt = 0; nt < 8; nt++) {
                uint32_t bh[2], bl[2];
                uint32_t bb = (uint32_t)(nk0 + nt * 8 + (lane & 7)) * 144u +
                              (uint32_t)(kt * 16 + ((lane >> 3) & 1) * 8) * 2u;
                ldsm2(bh, sb + OFF_KVH + bb);
                ldsm2(bl, sb + OFF_KVL + bb);
                mma_bf16(sc[nt], ah, bh);
                mma_bf16(sc[nt], ah, bl);
                mma_bf16(sc[nt], al, bh);
            }
        }

        // ---- exp + P split-store + row sums ----
        {
            float rs0 = 0.f, rs1 = 0.f;
            const int pr0 = mrow + (lane >> 2);
            #pragma unroll
            for (int nt = 0; nt < 8; nt++) {
                int col = e * 128 + nk0 + nt * 8 + (lane & 3) * 2;
                float p00 = __expf(sc[nt][0]), p01 = __expf(sc[nt][1]);
                float p10 = __expf(sc[nt][2]), p11 = __expf(sc[nt][3]);
                rs0 += p00 + p01; rs1 += p10 + p11;
                uint32_t hw, lw;
                pack_split(p00, p01, hw, lw);
                *(uint32_t*)(smc + OFF_PH + pr0 * 784 + col * 2) = hw;
                *(uint32_t*)(smc + OFF_PL + pr0 * 784 + col * 2) = lw;
                pack_split(p10, p11, hw, lw);
                *(uint32_t*)(smc + OFF_PH + (pr0 + 8) * 784 + col * 2) = hw;
                *(uint32_t*)(smc + OFF_PL + (pr0 + 8) * 784 + col * 2) = lw;
            }
            rs0 += __shfl_xor_sync(0xffffffffu, rs0, 1);
            rs0 += __shfl_xor_sync(0xffffffffu, rs0, 2);
            rs1 += __shfl_xor_sync(0xffffffffu, rs1, 1);
            rs1 += __shfl_xor_sync(0xffffffffu, rs1, 2);
            if ((lane & 3) == 0) {
                atomicAdd(&ssum[pr0], rs0);
                atomicAdd(&ssum[pr0 + 8], rs1);
            }
        }
        __syncthreads();   // QK reads done; P stores visible

        #pragma unroll
        for (int i = 0; i < 8; i++) {          // STS V (overwrite K)
            int f = tid + i * NT, row = f >> 4, g = f & 15;
            float4 val = kvreg[i];
            uint32_t h0, l0, h1, l1;
            pack_split(val.x, val.y, h0, l0);
            pack_split(val.z, val.w, h1, l1);
            *(uint2*)(smc + OFF_KVH + row * 144 + g * 8) = make_uint2(h0, h1);
            *(uint2*)(smc + OFF_KVL + row * 144 + g * 8) = make_uint2(l0, l1);
        }
        if (e < e1) {   // prefetch next K
            const float* kb = k + (size_t)(b * Sc + (c + e) * Wn) * 1024 + hb;
            #pragma unroll
            for (int i = 0; i < 8; i++) {
                int f = tid + i * NT;
                kvreg[i] = *(const float4*)(kb + (size_t)(f >> 4) * 1024 + (f & 15) * 4);
            }
        }
        __syncthreads();   // V visible

        // ---- PV: warp tile 16 rows x 32 dims, K=128, 3 passes ----
        #pragma unroll
        for (int kt = 0; kt < 8; kt++) {
            uint32_t ph[4], pl[4];
            uint32_t ab = (uint32_t)(mrow + (lane & 15)) * 784u +
                          (uint32_t)(e * 128 + kt * 16 + (lane >> 4) * 8) * 2u;
            ldsm4(ph, sb + OFF_PH + ab);
            ldsm4(pl, sb + OFF_PL + ab);
            #pragma unroll
            for (int nt = 0; nt < 4; nt++) {
                uint32_t vh[2], vl[2];
                uint32_t bb = (uint32_t)(kt * 16 + (lane & 15)) * 144u +
                              (uint32_t)(nv0 + nt * 8) * 2u;
                ldsm2t(vh, sb + OFF_KVH + bb);
                ldsm2t(vl, sb + OFF_KVL + bb);
                mma_bf16(o[nt], ph, vh);
                mma_bf16(o[nt], ph, vl);
                mma_bf16(o[nt], pl, vh);
            }
        }
    }
    __syncthreads();

    // ---- out = O * inv ----
    {
        const int r0 = mrow + (lane >> 2);
        const float i0 = 1.0f / ssum[r0], i8 = 1.0f / ssum[r0 + 8];
        float* ob  = out + ((size_t)(b * Sc + s0 + r0) * Hc + h) * 64;
        float* ob8 = out + ((size_t)(b * Sc + s0 + r0 + 8) * Hc + h) * 64;
        #pragma unroll
        for (int nt = 0; nt < 4; nt++) {
            int dim = nv0 + nt * 8 + (lane & 3) * 2;
            *(float2*)(ob + dim)  = make_float2(o[nt][0] * i0, o[nt][1] * i0);
            *(float2*)(ob8 + dim) = make_float2(o[nt][2] * i8, o[nt][3] * i8);
        }
    }

    // ---- attn = (Ph + Pl) * inv, fp32 (padded e -> inv) ----
    {
        const int row = tid >> 2, seg = tid & 3;
        const float inv = 1.0f / ssum[row];
        float* ab = attn + ((size_t)(b * Sc + s0 + row) * Hc + h) * 384;
        #pragma unroll
        for (int i = 0; i < 24; i++) {
            int col = seg * 96 + i * 4;
            int e = col >> 7;
            float4 oval;
            if (e < e0 || e > e1) {
                oval = make_float4(inv, inv, inv, inv);
            } else {
                uint2 hw = *(const uint2*)(smc + OFF_PH + row * 784 + col * 2);
                uint2 lw = *(const uint2*)(smc + OFF_PL + row * 784 + col * 2);
                oval.x = (blo(hw.x) + blo(lw.x)) * inv;
                oval.y = (bhi(hw.x) + bhi(lw.x)) * inv;
                oval.z = (blo(hw.y) + blo(lw.y)) * inv;
                oval.w = (bhi(hw.y) + bhi(lw.y)) * inv;
            }
            *(float4*)(ab + col) = oval;
        }
    }
}

extern "C" void kernel_launch(void* const* d_in, const int* in_sizes, int n_in,
                              void* d_out, int out_size)
{
    const float* q = (const float*)d_in[0];
    const float* k = (const float*)d_in[1];
    const float* v = (const float*)d_in[2];
    float* out  = (float*)d_out;
    float* attn = out + (size_t)Bc * Sc * Hc * 64;

    cudaFuncSetAttribute(swa_mma_kernel,
                         cudaFuncAttributeMaxDynamicSharedMemorySize, SMEM_BYTES);
    dim3 grid(Cc * 2, Hc, Bc);   // (chunk*2 + half, head, batch)
    swa_mma_kernel<<<grid, NT, SMEM_BYTES>>>(q, k, v, out, attn);
}

// round 9
// speedup vs baseline: 2.3134x; 1.0201x over previous
#include <cuda_runtime.h>
#include <cstdint>

// Sliding-window (no-overlap) attention, mma.sync bf16-split, register-P flash style.
// B=4,S=8192,H=16,D=64,w=128,C=64. Block=(chunk,head,batch): 128 queries, 256 thr.
// d_out = out [B,S,H,64] then attn [B,S,H,384].

constexpr int Bc = 4, Sc = 8192, Hc = 16, Wn = 128, Cc = 64, NT = 256;

// smem offsets (bytes). rows have 144B stride (128B data + 16B pad).
constexpr uint32_t OFF_QH = 0;           // Q hi [128][72] bf16
constexpr uint32_t OFF_QL = 18432;
constexpr uint32_t OFF_KH = 36864;       // K hi [128 kpos][72]
constexpr uint32_t OFF_KL = 55296;
constexpr uint32_t OFF_VH = 73728;       // V hi [128 kpos][72]
constexpr uint32_t OFF_VL = 92160;
constexpr uint32_t OFF_SSUM = 110592;    // 128 floats
constexpr uint32_t SMEM_BYTES = 110592 + 512;

__device__ __forceinline__ uint32_t su32(const void* p) {
    uint32_t a;
    asm("{ .reg .u64 t; cvta.to.shared.u64 t, %1; cvt.u32.u64 %0, t; }" : "=r"(a) : "l"(p));
    return a;
}
__device__ __forceinline__ void pack_split(float v0, float v1, uint32_t& hw, uint32_t& lw) {
    asm("cvt.rn.bf16x2.f32 %0, %1, %2;" : "=r"(hw) : "f"(v1), "f"(v0));
    float r0 = v0 - __uint_as_float(hw << 16);
    float r1 = v1 - __uint_as_float(hw & 0xffff0000u);
    asm("cvt.rn.bf16x2.f32 %0, %1, %2;" : "=r"(lw) : "f"(r1), "f"(r0));
}
__device__ __forceinline__ void ldsm4(uint32_t* r, uint32_t a) {
    asm volatile("ldmatrix.sync.aligned.m8n8.x4.shared.b16 {%0,%1,%2,%3}, [%4];"
        : "=r"(r[0]), "=r"(r[1]), "=r"(r[2]), "=r"(r[3]) : "r"(a));
}
__device__ __forceinline__ void ldsm4t(uint32_t* r, uint32_t a) {
    asm volatile("ldmatrix.sync.aligned.m8n8.x4.trans.shared.b16 {%0,%1,%2,%3}, [%4];"
        : "=r"(r[0]), "=r"(r[1]), "=r"(r[2]), "=r"(r[3]) : "r"(a));
}
__device__ __forceinline__ void mma_bf16(float* d, const uint32_t* a, const uint32_t* b) {
    asm volatile("mma.sync.aligned.m16n8k16.row.col.f32.bf16.bf16.f32 "
        "{%0,%1,%2,%3}, {%4,%5,%6,%7}, {%8,%9}, {%0,%1,%2,%3};"
        : "+f"(d[0]), "+f"(d[1]), "+f"(d[2]), "+f"(d[3])
        : "r"(a[0]), "r"(a[1]), "r"(a[2]), "r"(a[3]), "r"(b[0]), "r"(b[1]));
}

// split-convert a 128x64 fp32 tile (8 float4/thread) into hi/lo bf16 smem tiles
__device__ __forceinline__ void sts_split(const float4* reg, char* smc,
                                          uint32_t oH, uint32_t oL, int tid) {
    #pragma unroll
    for (int i = 0; i < 8; i++) {
        int f = tid + i * NT, row = f >> 4, g = f & 15;
        float4 val = reg[i];
        uint32_t h0, l0, h1, l1;
        pack_split(val.x, val.y, h0, l0);
        pack_split(val.z, val.w, h1, l1);
        *(uint2*)(smc + oH + row * 144 + g * 8) = make_uint2(h0, h1);
        *(uint2*)(smc + oL + row * 144 + g * 8) = make_uint2(l0, l1);
    }
}
__device__ __forceinline__ void ldg_tile(float4* reg, const float* base, int tid) {
    #pragma unroll
    for (int i = 0; i < 8; i++) {
        int f = tid + i * NT;
        reg[i] = *(const float4*)(base + (size_t)(f >> 4) * 1024 + (f & 15) * 4);
    }
}

__global__ void __launch_bounds__(NT, 1)
swa_mma_kernel(const float* __restrict__ q, const float* __restrict__ k,
               const float* __restrict__ v, float* __restrict__ out,
               float* __restrict__ attn)
{
    extern __shared__ char smc[];
    const uint32_t sb = su32(smc);
    const int tid = threadIdx.x, wid = tid >> 5, lane = tid & 31;
    const int c = blockIdx.x, h = blockIdx.y, b = blockIdx.z;
    const int s0 = c * Wn;
    const int e0 = (c > 0) ? 0 : 1, e1 = (c < Cc - 1) ? 2 : 1;

    float* ssum = (float*)(smc + OFF_SSUM);
    if (tid < 128) ssum[tid] = 128.0f * (float)(e0 + 2 - e1);

    const size_t hb = (size_t)h * 64;
    const float* kbase = k + (size_t)(b * Sc) * 1024 + hb;
    const float* vbase = v + (size_t)(b * Sc) * 1024 + hb;

    // ---- prologue: K_e0 LDG, Q split-STS, K/V_e0 split-STS ----
    float4 kreg[8], vreg[8];
    ldg_tile(kreg, kbase + (size_t)(c - 1 + e0) * Wn * 1024, tid);
    {
        float4 qreg[8];
        ldg_tile(qreg, q + (size_t)(b * Sc + s0) * 1024 + hb, tid);
        sts_split(qreg, smc, OFF_QH, OFF_QL, tid);
    }
    ldg_tile(vreg, vbase + (size_t)(c - 1 + e0) * Wn * 1024, tid);
    sts_split(kreg, smc, OFF_KH, OFF_KL, tid);
    sts_split(vreg, smc, OFF_VH, OFF_VL, tid);
    __syncthreads();

    const int mrow = wid * 16;
    const int r0 = mrow + (lane >> 2);

    // ---- Q A-fragments, cached for all e ----
    uint32_t ah[4][4], al[4][4];
    #pragma unroll
    for (int kt = 0; kt < 4; kt++) {
        uint32_t ab = (uint32_t)(mrow + (lane & 15)) * 144u +
                      (uint32_t)(kt * 16 + (lane >> 4) * 8) * 2u;
        ldsm4(ah[kt], sb + OFF_QH + ab);
        ldsm4(al[kt], sb + OFF_QL + ab);
    }

    float o[8][4];
    #pragma unroll
    for (int i = 0; i < 8; i++) { o[i][0] = o[i][1] = o[i][2] = o[i][3] = 0.f; }

    float* aprow  = attn + ((size_t)(b * Sc + s0 + r0) * Hc + h) * 384;
    float* aprow8 = aprow + (size_t)8 * Hc * 384;

    for (int e = e0; e <= e1; e++) {
        if (e < e1) {   // prefetch next chunk
            ldg_tile(kreg, kbase + (size_t)(c + e) * Wn * 1024, tid);
            ldg_tile(vreg, vbase + (size_t)(c + e) * Wn * 1024, tid);
        }
        float rs0 = 0.f, rs1 = 0.f;
        #pragma unroll 2
        for (int pair = 0; pair < 8; pair++) {
            // ---- QK: n16 strip (cols pair*16..+15), 3 split passes ----
            float sc0[4] = {0.f, 0.f, 0.f, 0.f};
            float sc1[4] = {0.f, 0.f, 0.f, 0.f};
            #pragma unroll
            for (int kt = 0; kt < 4; kt++) {
                const int mat = lane >> 3;
                uint32_t ba = (uint32_t)(pair * 16 + (mat >> 1) * 8 + (lane & 7)) * 144u +
                              (uint32_t)(kt * 16 + (mat & 1) * 8) * 2u;
                uint32_t bh[4], bl[4];
                ldsm4(bh, sb + OFF_KH + ba);
                ldsm4(bl, sb + OFF_KL + ba);
                mma_bf16(sc0, ah[kt], bh);     mma_bf16(sc1, ah[kt], bh + 2);
                mma_bf16(sc0, ah[kt], bl);     mma_bf16(sc1, ah[kt], bl + 2);
                mma_bf16(sc0, al[kt], bh);     mma_bf16(sc1, al[kt], bh + 2);
            }
            // ---- exp, row sums, unnormalized attn write, pack P frags ----
            float e00 = __expf(sc0[0]), e01 = __expf(sc0[1]);
            float e02 = __expf(sc0[2]), e03 = __expf(sc0[3]);
            float e10 = __expf(sc1[0]), e11 = __expf(sc1[1]);
            float e12 = __expf(sc1[2]), e13 = __expf(sc1[3]);
            rs0 += e00 + e01 + e10 + e11;
            rs1 += e02 + e03 + e12 + e13;
            const int col = e * 128 + pair * 16 + (lane & 3) * 2;
            *(float2*)(aprow  + col)     = make_float2(e00, e01);
            *(float2*)(aprow  + col + 8) = make_float2(e10, e11);
            *(float2*)(aprow8 + col)     = make_float2(e02, e03);
            *(float2*)(aprow8 + col + 8) = make_float2(e12, e13);
            uint32_t ph[4], pl[4];
            pack_split(e00, e01, ph[0], pl[0]);
            pack_split(e02, e03, ph[1], pl[1]);
            pack_split(e10, e11, ph[2], pl[2]);
            pack_split(e12, e13, ph[3], pl[3]);
            // ---- PV: kpos strip pair*16..+15 against V, 3 split passes ----
            #pragma unroll
            for (int nvp = 0; nvp < 4; nvp++) {
                uint32_t va = (uint32_t)(pair * 16 + (lane & 15)) * 144u +
                              (uint32_t)(nvp * 16 + (lane >> 4) * 8) * 2u;
                uint32_t vh[4], vl[4];
                ldsm4t(vh, sb + OFF_VH + va);
                ldsm4t(vl, sb + OFF_VL + va);
                mma_bf16(o[2 * nvp],     ph, vh);     mma_bf16(o[2 * nvp + 1], ph, vh + 2);
                mma_bf16(o[2 * nvp],     ph, vl);     mma_bf16(o[2 * nvp + 1], ph, vl + 2);
                mma_bf16(o[2 * nvp],     pl, vh);     mma_bf16(o[2 * nvp + 1], pl, vh + 2);
            }
        }
        rs0 += __shfl_xor_sync(0xffffffffu, rs0, 1);
        rs0 += __shfl_xor_sync(0xffffffffu, rs0, 2);
        rs1 += __shfl_xor_sync(0xffffffffu, rs1, 1);
        rs1 += __shfl_xor_sync(0xffffffffu, rs1, 2);
        if ((lane & 3) == 0) {
            atomicAdd(&ssum[r0], rs0);
            atomicAdd(&ssum[r0 + 8], rs1);
        }
        __syncthreads();   // K/V buffers free; (last e: sums complete)
        if (e < e1) {
            sts_split(kreg, smc, OFF_KH, OFF_KL, tid);
            sts_split(vreg, smc, OFF_VH, OFF_VL, tid);
        }
        __syncthreads();   // buffers valid / ssum visible
    }

    // ---- out = O * inv ----
    {
        const float i0 = 1.0f / ssum[r0], i8 = 1.0f / ssum[r0 + 8];
        float* ob  = out + ((size_t)(b * Sc + s0 + r0) * Hc + h) * 64;
        float* ob8 = ob + (size_t)8 * Hc * 64;
        #pragma unroll
        for (int nt = 0; nt < 8; nt++) {
            const int dim = nt * 8 + (lane & 3) * 2;
            *(float2*)(ob  + dim) = make_float2(o[nt][0] * i0, o[nt][1] * i0);
            *(float2*)(ob8 + dim) = make_float2(o[nt][2] * i8, o[nt][3] * i8);
        }
    }

    // ---- attn normalize pass (block-local, L2-hot) ----
    {
        const int row = tid >> 1, half = tid & 1;
        const float inv = 1.0f / ssum[row];
        float* ar = attn + ((size_t)(b * Sc + s0 + row) * Hc + h) * 384;
        #pragma unroll 4
        for (int i = 0; i < 48; i++) {
            const int col = half * 192 + i * 4;
            const int e = col >> 7;
            float4 oval;
            if (e < e0 || e > e1) {
                oval = make_float4(inv, inv, inv, inv);
            } else {
                oval = *(const float4*)(ar + col);
                oval.x *= inv; oval.y *= inv; oval.z *= inv; oval.w *= inv;
            }
            *(float4*)(ar + col) = oval;
        }
    }
}

extern "C" void kernel_launch(void* const* d_in, const int* in_sizes, int n_in,
                              void* d_out, int out_size)
{
    const float* q = (const float*)d_in[0];
    const float* k = (const float*)d_in[1];
    const float* v = (const float*)d_in[2];
    float* out  = (float*)d_out;
    float* attn = out + (size_t)Bc * Sc * Hc * 64;

    cudaFuncSetAttribute(swa_mma_kernel,
                         cudaFuncAttributeMaxDynamicSharedMemorySize, SMEM_BYTES);
    dim3 grid(Cc, Hc, Bc);
    swa_mma_kernel<<<grid, NT, SMEM_BYTES>>>(q, k, v, out, attn);
}